// round 7
// baseline (speedup 1.0000x reference)
#include <cuda_runtime.h>
#include <cstdint>
#include <math_constants.h>

#define BB   2
#define NN   8192
#define KK   10
#define KS   11            // KK + 1 slot absorbs self
#define G    16
#define NCB  (G * G * G)   // 4096 cells per batch
#define TPB  128

// Scratch (no device allocation allowed)
__device__ float4 g_q[BB * NN];          // {p1-p2, 0} original order
__device__ float4 g_sortedPts[BB * NN];  // {-2x,-2y,-2z,|p|^2} cell-sorted
__device__ float4 g_sortedQry[BB * NN];  // {x,y,z,|p|^2} cell-sorted
__device__ float4 g_sortedQ[BB * NN];    // q cell-sorted
__device__ int    g_cellOf[BB * NN];
__device__ int    g_cnt[BB * NCB];
__device__ int2   g_meta[BB * NCB];      // {start, count} per cell
__device__ int    g_cursor[BB * NCB];
__device__ float  g_edges[G + 1];
__device__ float  g_acc;
__device__ unsigned int g_bdone;

__device__ __forceinline__ int cell_coord(float v) {
    float u = normcdff(v);                 // iid N(0,1) -> Uniform(0,1)
    int c = (int)(u * (float)G);
    return min(G - 1, max(0, c));
}

__global__ void init_kernel() {
    int i = blockIdx.x * blockDim.x + threadIdx.x;
    if (i < BB * NCB) g_cnt[i] = 0;
    if (i <= G) {
        g_edges[i] = (i == 0) ? -1e30f
                   : (i == G) ?  1e30f
                   : 1.41421356237f * erfinvf(2.0f * (float)i / (float)G - 1.0f);
    }
    if (i == 0) { g_acc = 0.0f; g_bdone = 0u; }
}

__global__ void prep_kernel(const float* __restrict__ p1,
                            const float* __restrict__ p2) {
    int i = blockIdx.x * blockDim.x + threadIdx.x;
    if (i >= BB * NN) return;
    int b = i / NN;
    float x = p1[3 * i + 0], y = p1[3 * i + 1], z = p1[3 * i + 2];
    float a = p2[3 * i + 0], bb = p2[3 * i + 1], c = p2[3 * i + 2];
    g_q[i] = make_float4(x - a, y - bb, z - c, 0.0f);
    int cc = (cell_coord(z) * G + cell_coord(y)) * G + cell_coord(x);
    g_cellOf[i] = cc;
    atomicAdd(&g_cnt[b * NCB + cc], 1);
}

// One block per batch; 1024 threads x 4 cells = 4096. Exclusive scan of counts.
__global__ __launch_bounds__(1024) void scan_kernel() {
    __shared__ int ssum[1024];
    int b = blockIdx.x;
    int t = threadIdx.x;
    int base = b * NCB + t * 4;
    int c0 = g_cnt[base + 0], c1 = g_cnt[base + 1];
    int c2 = g_cnt[base + 2], c3 = g_cnt[base + 3];
    int s = c0 + c1 + c2 + c3;
    ssum[t] = s;
    __syncthreads();
    for (int off = 1; off < 1024; off <<= 1) {
        int v = 0;
        if (t >= off) v = ssum[t - off];
        __syncthreads();
        if (t >= off) ssum[t] += v;
        __syncthreads();
    }
    int st = ssum[t] - s;  // exclusive prefix
    g_meta[base + 0] = make_int2(st, c0);            g_cursor[base + 0] = st;  st += c0;
    g_meta[base + 1] = make_int2(st, c1);            g_cursor[base + 1] = st;  st += c1;
    g_meta[base + 2] = make_int2(st, c2);            g_cursor[base + 2] = st;  st += c2;
    g_meta[base + 3] = make_int2(st, c3);            g_cursor[base + 3] = st;
}

__global__ void scatter_kernel(const float* __restrict__ p1) {
    int i = blockIdx.x * blockDim.x + threadIdx.x;
    if (i >= BB * NN) return;
    int b = i / NN;
    int cc = g_cellOf[i];
    int pos = atomicAdd(&g_cursor[b * NCB + cc], 1);
    float x = p1[3 * i + 0], y = p1[3 * i + 1], z = p1[3 * i + 2];
    float w = fmaf(z, z, fmaf(y, y, x * x));
    long o = (long)b * NN + pos;
    g_sortedPts[o] = make_float4(-2.0f * x, -2.0f * y, -2.0f * z, w);
    g_sortedQry[o] = make_float4(x, y, z, w);
    g_sortedQ[o]   = g_q[i];
}

// Branchless sorted insert into ascending 11-list.
__device__ __forceinline__ void insert11(float v, int vi,
                                         float* __restrict__ dist,
                                         int* __restrict__ nn) {
    bool p[KS];
#pragma unroll
    for (int k = 0; k < KS; ++k) p[k] = v < dist[k];
#pragma unroll
    for (int k = KS - 1; k >= 1; --k) {
        dist[k] = p[k] ? (p[k - 1] ? dist[k - 1] : v) : dist[k];
        nn[k]   = p[k] ? (p[k - 1] ? nn[k - 1]  : vi) : nn[k];
    }
    dist[0] = p[0] ? v  : dist[0];
    nn[0]   = p[0] ? vi : nn[0];
}

// grid (NN/TPB, BB): one thread per cell-sorted query. Expanding Chebyshev
// shells with exact cell-box pruning; fused L1-loss epilogue + finalize.
__global__ __launch_bounds__(TPB) void knn_loss_kernel(float* __restrict__ out,
                                                       int nblocks) {
    __shared__ float sedges[G + 1];
    __shared__ float wsum[TPB / 32];
    if (threadIdx.x <= G) sedges[threadIdx.x] = g_edges[threadIdx.x];
    __syncthreads();

    const int b = blockIdx.y;
    const int s = blockIdx.x * TPB + threadIdx.x;      // sorted position
    const long qb = (long)b * NN;
    const float4 me = g_sortedQry[qb + s];

    const int cx = cell_coord(me.x);
    const int cy = cell_coord(me.y);
    const int cz = cell_coord(me.z);

    float dist[KS];
    int   nn[KS];
#pragma unroll
    for (int k = 0; k < KS; ++k) { dist[k] = CUDART_INF_F; nn[k] = -1; }

    for (int r = 0; r < G; ++r) {
        int zlo = max(cz - r, 0), zhi = min(cz + r, G - 1);
        int ylo = max(cy - r, 0), yhi = min(cy + r, G - 1);
        int xlo = max(cx - r, 0), xhi = min(cx + r, G - 1);
        for (int az = zlo; az <= zhi; ++az) {
            int dz = abs(az - cz);
            for (int ay = ylo; ay <= yhi; ++ay) {
                int dzy = max(dz, abs(ay - cy));
                for (int ax = xlo; ax <= xhi; ++ax) {
                    int ch = max(dzy, abs(ax - cx));
                    if (ch != r) continue;          // only the shell surface
                    int cell = (az * G + ay) * G + ax;
                    int2 mt = __ldg(&g_meta[b * NCB + cell]);
                    if (mt.y == 0) continue;
                    if (r >= 2) {                   // exact cell-box prune
                        float ddx = fmaxf(fmaxf(sedges[ax] - me.x, me.x - sedges[ax + 1]), 0.0f);
                        float ddy = fmaxf(fmaxf(sedges[ay] - me.y, me.y - sedges[ay + 1]), 0.0f);
                        float ddz = fmaxf(fmaxf(sedges[az] - me.z, me.z - sedges[az + 1]), 0.0f);
                        float d2box = fmaf(ddx, ddx, fmaf(ddy, ddy, ddz * ddz));
                        if (d2box >= dist[KS - 1]) continue;
                    }
                    int jend = mt.x + mt.y;
                    for (int j = mt.x; j < jend; ++j) {
                        float4 c = __ldg(&g_sortedPts[qb + j]);
                        float d2 = fmaf(c.x, me.x,
                                   fmaf(c.y, me.y,
                                   fmaf(c.z, me.z, me.w + c.w)));
                        if (d2 < dist[KS - 1]) insert11(d2, j, dist, nn);
                    }
                }
            }
        }
        // stop test: min distance to region outside the scanned box [c-r,c+r]^3
        float dmin = CUDART_INF_F;
        if (cx - r > 0)     dmin = fminf(dmin, me.x - sedges[cx - r]);
        if (cx + r + 1 < G) dmin = fminf(dmin, sedges[cx + r + 1] - me.x);
        if (cy - r > 0)     dmin = fminf(dmin, me.y - sedges[cy - r]);
        if (cy + r + 1 < G) dmin = fminf(dmin, sedges[cy + r + 1] - me.y);
        if (cz - r > 0)     dmin = fminf(dmin, me.z - sedges[cz - r]);
        if (cz + r + 1 < G) dmin = fminf(dmin, sedges[cz + r + 1] - me.z);
        if (dmin * dmin >= dist[KS - 1]) break;    // inf>=inf also terminates
    }

    // Epilogue: lap1-lap2 = mean_k q[nbr] - q_self (self = sorted pos s)
    float sx = 0.0f, sy = 0.0f, sz = 0.0f;
#pragma unroll
    for (int k = 0; k < KS; ++k) {
        int j = nn[k];
        if (j != s && j >= 0) {
            float4 v = __ldg(&g_sortedQ[qb + j]);
            sx += v.x; sy += v.y; sz += v.z;
        }
    }
    float4 myq = g_sortedQ[qb + s];
    const float inv_k = 1.0f / (float)KK;
    float lx = sx * inv_k - myq.x;
    float ly = sy * inv_k - myq.y;
    float lz = sz * inv_k - myq.z;
    float contrib = fabsf(lx) + fabsf(ly) + fabsf(lz);

#pragma unroll
    for (int off = 16; off > 0; off >>= 1)
        contrib += __shfl_down_sync(0xffffffffu, contrib, off);
    if ((threadIdx.x & 31) == 0) wsum[threadIdx.x >> 5] = contrib;
    __syncthreads();
    if (threadIdx.x == 0) {
        float ssum = 0.0f;
#pragma unroll
        for (int w = 0; w < TPB / 32; ++w) ssum += wsum[w];
        atomicAdd(&g_acc, ssum);
        __threadfence();
        unsigned int done = atomicAdd(&g_bdone, 1u);
        if (done == (unsigned int)(nblocks - 1)) {
            float acc = *((volatile float*)&g_acc);
            out[0] = acc * (1.0f / (float)(BB * NN * 3));
        }
    }
}

extern "C" void kernel_launch(void* const* d_in, const int* in_sizes, int n_in,
                              void* d_out, int out_size) {
    const float* p1 = (const float*)d_in[0];
    const float* p2 = (const float*)d_in[1];
    float* out = (float*)d_out;

    init_kernel<<<(BB * NCB + 1023) / 1024, 1024>>>();
    prep_kernel<<<(BB * NN + 255) / 256, 256>>>(p1, p2);
    scan_kernel<<<BB, 1024>>>();
    scatter_kernel<<<(BB * NN + 255) / 256, 256>>>(p1);
    dim3 grid(NN / TPB, BB);
    knn_loss_kernel<<<grid, TPB>>>(out, (NN / TPB) * BB);
}

// round 8
// speedup vs baseline: 4.5311x; 4.5311x over previous
#include <cuda_runtime.h>
#include <cstdint>
#include <math_constants.h>

#define BB   2
#define NN   8192
#define KK   10
#define KS   11            // KK + 1 slot absorbs self
#define G    16
#define NCB  (G * G * G)   // 4096 cells (12-bit Morton)
#define TPB  128
#define TILE 1024
#define SEG  2
#define SEGLEN (NN / SEG)  // 4096
#define WIN  256           // warm-start window (sorted positions)

// Scratch (no device allocation allowed)
__device__ float4 g_q[BB * NN];          // {p1-p2, 0} original order
__device__ float4 g_sortedPts[BB * NN];  // {-2x,-2y,-2z,|p|^2} Morton-sorted (candidate form)
__device__ float4 g_sortedQ[BB * NN];    // q Morton-sorted
__device__ int    g_cellOf[BB * NN];
__device__ int    g_cnt[BB * NCB];
__device__ int    g_cursor[BB * NCB];
__device__ float  g_top_d[SEG * BB * NN * KS];
__device__ int    g_top_i[SEG * BB * NN * KS];
__device__ float  g_acc;
__device__ unsigned int g_bdone;

__device__ __forceinline__ int cell_coord(float v) {
    float u = normcdff(v);                 // iid N(0,1) -> Uniform(0,1)
    int c = (int)(u * (float)G);
    return min(G - 1, max(0, c));
}

__device__ __forceinline__ int spread4(int v) {
    return (v & 1) | ((v & 2) << 2) | ((v & 4) << 4) | ((v & 8) << 6);
}

__global__ void init_kernel() {
    int i = blockIdx.x * blockDim.x + threadIdx.x;
    if (i < BB * NCB) g_cnt[i] = 0;
    if (i == 0) { g_acc = 0.0f; g_bdone = 0u; }
}

__global__ void prep_kernel(const float* __restrict__ p1,
                            const float* __restrict__ p2) {
    int i = blockIdx.x * blockDim.x + threadIdx.x;
    if (i >= BB * NN) return;
    int b = i / NN;
    float x = p1[3 * i + 0], y = p1[3 * i + 1], z = p1[3 * i + 2];
    float a = p2[3 * i + 0], bb = p2[3 * i + 1], c = p2[3 * i + 2];
    g_q[i] = make_float4(x - a, y - bb, z - c, 0.0f);
    int code = spread4(cell_coord(x))
             | (spread4(cell_coord(y)) << 1)
             | (spread4(cell_coord(z)) << 2);    // 12-bit Morton
    g_cellOf[i] = code;
    atomicAdd(&g_cnt[b * NCB + code], 1);
}

// One block per batch; 1024 threads x 4 cells = 4096. Exclusive scan of counts.
__global__ __launch_bounds__(1024) void scan_kernel() {
    __shared__ int ssum[1024];
    int b = blockIdx.x;
    int t = threadIdx.x;
    int base = b * NCB + t * 4;
    int c0 = g_cnt[base + 0], c1 = g_cnt[base + 1];
    int c2 = g_cnt[base + 2], c3 = g_cnt[base + 3];
    int s = c0 + c1 + c2 + c3;
    ssum[t] = s;
    __syncthreads();
    for (int off = 1; off < 1024; off <<= 1) {
        int v = 0;
        if (t >= off) v = ssum[t - off];
        __syncthreads();
        if (t >= off) ssum[t] += v;
        __syncthreads();
    }
    int st = ssum[t] - s;  // exclusive prefix
    g_cursor[base + 0] = st;  st += c0;
    g_cursor[base + 1] = st;  st += c1;
    g_cursor[base + 2] = st;  st += c2;
    g_cursor[base + 3] = st;
}

__global__ void scatter_kernel(const float* __restrict__ p1) {
    int i = blockIdx.x * blockDim.x + threadIdx.x;
    if (i >= BB * NN) return;
    int b = i / NN;
    int cc = g_cellOf[i];
    int pos = atomicAdd(&g_cursor[b * NCB + cc], 1);
    float x = p1[3 * i + 0], y = p1[3 * i + 1], z = p1[3 * i + 2];
    float w = fmaf(z, z, fmaf(y, y, x * x));
    long o = (long)b * NN + pos;
    g_sortedPts[o] = make_float4(-2.0f * x, -2.0f * y, -2.0f * z, w);
    g_sortedQ[o]   = g_q[i];
}

// Branchless sorted insert into ascending 11-list (value+index).
__device__ __forceinline__ void insert11(float v, int vi,
                                         float* __restrict__ dist,
                                         int* __restrict__ nn) {
    bool p[KS];
#pragma unroll
    for (int k = 0; k < KS; ++k) p[k] = v < dist[k];
#pragma unroll
    for (int k = KS - 1; k >= 1; --k) {
        dist[k] = p[k] ? (p[k - 1] ? dist[k - 1] : v) : dist[k];
        nn[k]   = p[k] ? (p[k - 1] ? nn[k - 1]  : vi) : nn[k];
    }
    dist[0] = p[0] ? v  : dist[0];
    nn[0]   = p[0] ? vi : nn[0];
}

// Distance-only branchless insert (for the warm-threshold pass).
__device__ __forceinline__ void insertD(float v, float* __restrict__ d) {
    bool p[KS];
#pragma unroll
    for (int k = 0; k < KS; ++k) p[k] = v < d[k];
#pragma unroll
    for (int k = KS - 1; k >= 1; --k)
        d[k] = p[k] ? (p[k - 1] ? d[k - 1] : v) : d[k];
    d[0] = p[0] ? v : d[0];
}

__device__ __forceinline__ float dist2(float4 c, float4 me) {
    return fmaf(c.x, me.x, fmaf(c.y, me.y, fmaf(c.z, me.z, me.w + c.w)));
}

// grid: (NN/TPB, BB, SEG). One thread per Morton-sorted query.
__global__ __launch_bounds__(TPB) void knn_seg_kernel() {
    __shared__ float4 tileA[WIN];
    __shared__ float4 tile[TILE];

    const int b   = blockIdx.y;
    const int sg  = blockIdx.z;
    const int blk0 = blockIdx.x * TPB;
    const int s   = blk0 + threadIdx.x;          // sorted query position
    const int c0  = sg * SEGLEN;
    const long qb = (long)b * NN;
    const float4* __restrict__ cand = g_sortedPts + qb;

    // reconstruct query form {x,y,z,w} from candidate form
    const float4 cb = cand[s];
    const float4 me = make_float4(-0.5f * cb.x, -0.5f * cb.y, -0.5f * cb.z, cb.w);

    // ---------- Phase A: warm threshold from local Morton window ----------
    const int wlo = blk0 & ~(WIN - 1);           // 256-aligned, contains the block
#pragma unroll
    for (int j = threadIdx.x; j < WIN; j += TPB)
        tileA[j] = cand[wlo + j];
    __syncthreads();

    float dD[KS];
#pragma unroll
    for (int k = 0; k < KS; ++k) dD[k] = CUDART_INF_F;
    for (int j = 0; j < WIN; ++j)
        insertD(dist2(tileA[j], me), dD);
    const float thr0 = dD[KS - 1];   // upper bound on true 11th distance

    // ---------- Phase B: scan own segment with tight filter ----------
    float dist[KS];
    int   nn[KS];
#pragma unroll
    for (int k = 0; k < KS; ++k) { dist[k] = CUDART_INF_F; nn[k] = -1; }

    for (int t = c0; t < c0 + SEGLEN; t += TILE) {
        __syncthreads();
#pragma unroll
        for (int j = threadIdx.x; j < TILE; j += TPB)
            tile[j] = cand[t + j];
        __syncthreads();

        for (int j0 = 0; j0 < TILE; j0 += 8) {
            float d2v[8];
#pragma unroll
            for (int u = 0; u < 8; ++u)
                d2v[u] = dist2(tile[j0 + u], me);
            float mn = fminf(fminf(fminf(d2v[0], d2v[1]), fminf(d2v[2], d2v[3])),
                             fminf(fminf(d2v[4], d2v[5]), fminf(d2v[6], d2v[7])));
            float thrv = fminf(thr0, dist[KS - 1]);
            if (__any_sync(0xffffffffu, mn <= thrv)) {
#pragma unroll
                for (int u = 0; u < 8; ++u) {
                    bool p = d2v[u] <= thrv;
                    if (__any_sync(0xffffffffu, p)) {
                        float v = p ? d2v[u] : CUDART_INF_F;
                        insert11(v, t + j0 + u, dist, nn);
                    }
                }
            }
        }
    }

    long base = (((long)sg * BB + b) * NN + s) * KS;
#pragma unroll
    for (int k = 0; k < KS; ++k) {
        g_top_d[base + k] = dist[k];
        g_top_i[base + k] = nn[k];
    }
}

// One thread per query: 2-way merge of sorted 11-lists, skip self, take 10,
// then L1-loss contribution; last block finalizes the output.
__global__ __launch_bounds__(256) void merge_loss_kernel(float* __restrict__ out,
                                                         int nblocks) {
    __shared__ float wsum[256 / 32];

    int q  = blockIdx.x * blockDim.x + threadIdx.x;
    int b  = q / NN;
    int s  = q - b * NN;                 // sorted position (self index)

    long base0 = (((long)0 * BB + b) * NN + s) * KS;
    long base1 = (((long)1 * BB + b) * NN + s) * KS;

    float hd0 = g_top_d[base0], hd1 = g_top_d[base1];
    int   hi0 = g_top_i[base0], hi1 = g_top_i[base1];
    int   p0 = 1, p1 = 1;

    const float4* __restrict__ qv = g_sortedQ + (long)b * NN;
    float sx = 0.0f, sy = 0.0f, sz = 0.0f;
    int cnt = 0;

#pragma unroll
    for (int step = 0; step < KS + 1; ++step) {
        if (cnt >= KK) break;
        int idx;
        if (hd1 < hd0) {
            idx = hi1;
            hd1 = (p1 < KS) ? g_top_d[base1 + p1] : CUDART_INF_F;
            hi1 = (p1 < KS) ? g_top_i[base1 + p1] : -1;
            ++p1;
        } else {
            idx = hi0;
            hd0 = (p0 < KS) ? g_top_d[base0 + p0] : CUDART_INF_F;
            hi0 = (p0 < KS) ? g_top_i[base0 + p0] : -1;
            ++p0;
        }
        if (idx != s && idx >= 0) {
            float4 v = __ldg(&qv[idx]);
            sx += v.x; sy += v.y; sz += v.z;
            ++cnt;
        }
    }

    float4 myq = qv[s];
    const float inv_k = 1.0f / (float)KK;
    float lx = sx * inv_k - myq.x;
    float ly = sy * inv_k - myq.y;
    float lz = sz * inv_k - myq.z;
    float contrib = fabsf(lx) + fabsf(ly) + fabsf(lz);

#pragma unroll
    for (int off = 16; off > 0; off >>= 1)
        contrib += __shfl_down_sync(0xffffffffu, contrib, off);
    if ((threadIdx.x & 31) == 0) wsum[threadIdx.x >> 5] = contrib;
    __syncthreads();
    if (threadIdx.x == 0) {
        float ssum = 0.0f;
#pragma unroll
        for (int w = 0; w < 256 / 32; ++w) ssum += wsum[w];
        atomicAdd(&g_acc, ssum);
        __threadfence();
        unsigned int done = atomicAdd(&g_bdone, 1u);
        if (done == (unsigned int)(nblocks - 1)) {
            float acc = *((volatile float*)&g_acc);
            out[0] = acc * (1.0f / (float)(BB * NN * 3));
        }
    }
}

extern "C" void kernel_launch(void* const* d_in, const int* in_sizes, int n_in,
                              void* d_out, int out_size) {
    const float* p1 = (const float*)d_in[0];
    const float* p2 = (const float*)d_in[1];
    float* out = (float*)d_out;

    init_kernel<<<(BB * NCB + 1023) / 1024, 1024>>>();
    prep_kernel<<<(BB * NN + 255) / 256, 256>>>(p1, p2);
    scan_kernel<<<BB, 1024>>>();
    scatter_kernel<<<(BB * NN + 255) / 256, 256>>>(p1);
    dim3 grid(NN / TPB, BB, SEG);
    knn_seg_kernel<<<grid, TPB>>>();
    int nblocks = BB * NN / 256;
    merge_loss_kernel<<<nblocks, 256>>>(out, nblocks);
}